// round 2
// baseline (speedup 1.0000x reference)
#include <cuda_runtime.h>
#include <cstdint>

#define T_STEPS 10
#define IN_DIM  784
#define HID     256
#define NCLS    47
#define BATCH   4096

#define BI    (BATCH * IN_DIM)          /* 3,211,264  */
#define TOTAL (T_STEPS * BI)            /* 32,112,640 */

// RNG variant switch: 1 = jax_threefry_partitionable (modern JAX default),
//                     0 = original threefry path (legacy)
#define PARTITIONABLE 1

// Scratch (static __device__ arrays — no cudaMalloc anywhere)
__device__ float g_spikes[TOTAL];        // 128 MB: [T][B][784] spikes {0,1}
__device__ float g_vhid[BATCH * HID];    // membrane potential
__device__ float g_spkacc[BATCH * HID];  // Sum_t 2^(t-10) * spk_t (exact fp32)

__device__ __forceinline__ uint32_t rotl32(uint32_t x, int d) {
    return __funnelshift_l(x, x, d);
}
__device__ __forceinline__ float u01(uint32_t bits) {
    return __uint_as_float((bits >> 9) | 0x3f800000u) - 1.0f;
}

// threefry2x32 with key (0, 42): in/out through x0,x1
__device__ __forceinline__ void threefry_0_42(uint32_t& x0, uint32_t& x1) {
    const uint32_t ks0 = 0u;
    const uint32_t ks1 = 42u;
    const uint32_t ks2 = 0u ^ 42u ^ 0x1BD11BDAu;
    x0 += ks0; x1 += ks1;
#define RND(r) { x0 += x1; x1 = rotl32(x1, r); x1 ^= x0; }
    RND(13) RND(15) RND(26) RND(6)   x0 += ks1; x1 += ks2 + 1u;
    RND(17) RND(29) RND(16) RND(24)  x0 += ks2; x1 += ks0 + 2u;
    RND(13) RND(15) RND(26) RND(6)   x0 += ks0; x1 += ks1 + 3u;
    RND(17) RND(29) RND(16) RND(24)  x0 += ks1; x1 += ks2 + 4u;
    RND(13) RND(15) RND(26) RND(6)   x0 += ks2; x1 += ks0 + 5u;
#undef RND
}

// ---------------------------------------------------------------------------
// Kernel 1: JAX threefry -> Bernoulli spikes.
// ---------------------------------------------------------------------------
#if PARTITIONABLE
// Partitionable path: per element i, counts = (hi(i)=0, lo(i)=i) as uint64 iota;
// 32-bit output = out0 ^ out1. u = bitcast((bits>>9)|0x3f800000)-1.
__global__ __launch_bounds__(256)
void rng_spikes_kernel(const float* __restrict__ x) {
    uint32_t base = (blockIdx.x * blockDim.x + threadIdx.x) * 4u;
    if (base >= (uint32_t)TOTAL) return;
    float v[4];
#pragma unroll
    for (int e = 0; e < 4; ++e) {
        uint32_t i = base + e;
        uint32_t x0 = 0u, x1 = i;          // count hi = 0 (size < 2^32), lo = i
        threefry_0_42(x0, x1);
        uint32_t bits = x0 ^ x1;
        uint32_t rem = i % (uint32_t)BI;   // -> b*784 + j
        float px = __ldg(&x[rem]);
        v[e] = (u01(bits) < px) ? 1.0f : 0.0f;
    }
    *reinterpret_cast<float4*>(g_spikes + base) = make_float4(v[0], v[1], v[2], v[3]);
}
#define RNG_GRID ((TOTAL / 4 + 255) / 256)
#else
// Original path: pair i = (i, i + TOTAL/2), out[i]=f(x0), out[i+HALF]=f(x1)
#define HALF (TOTAL / 2)
__global__ __launch_bounds__(256)
void rng_spikes_kernel(const float* __restrict__ x) {
    uint32_t i = blockIdx.x * blockDim.x + threadIdx.x;
    if (i >= (uint32_t)HALF) return;
    uint32_t x0 = i, x1 = i + (uint32_t)HALF;
    threefry_0_42(x0, x1);
    {
        uint32_t rem = i % (uint32_t)BI;
        g_spikes[i] = (u01(x0) < __ldg(&x[rem])) ? 1.0f : 0.0f;
    }
    {
        uint32_t idx = i + (uint32_t)HALF;
        uint32_t rem = idx % (uint32_t)BI;
        g_spikes[idx] = (u01(x1) < __ldg(&x[rem])) ? 1.0f : 0.0f;
    }
}
#define RNG_GRID (HALF / 256)
#endif

// ---------------------------------------------------------------------------
// Kernel 2: per-timestep hidden layer (fused SGEMM + LIF + weighted-spike acc)
//   I = spikes_t @ W1 + b1 ; v += (I - v)*0.5 ; spk = (v>=1) ; v *= (1-spk)
//   g_spkacc (+)= 2^(t-10) * spk
// ---------------------------------------------------------------------------
#define BM 64
#define BN 64
#define BK 16
#define APAD 4

__global__ __launch_bounds__(256)
void hidden_kernel(const float* __restrict__ W1,
                   const float* __restrict__ b1,
                   int t, float ct) {
    __shared__ float As[BK][BM + APAD];
    __shared__ float Bs[BK][BN];

    const int tid = threadIdx.x;
    const int bm  = blockIdx.x;
    const int bn  = blockIdx.y;
    const int tx  = tid & 15;
    const int ty  = tid >> 4;

    const float* Abase = g_spikes + (size_t)t * BI + (size_t)bm * BM * IN_DIM;

    const int arow = tid >> 2;
    const int akq  = (tid & 3) * 4;
    const int bk   = tid >> 4;
    const int bq   = (tid & 15) * 4;

    float acc[4][4] = {};

    for (int k0 = 0; k0 < IN_DIM; k0 += BK) {
        float4 av = *reinterpret_cast<const float4*>(Abase + (size_t)arow * IN_DIM + k0 + akq);
        float4 bv = *reinterpret_cast<const float4*>(W1 + (size_t)(k0 + bk) * HID + bn * BN + bq);

        __syncthreads();
        As[akq + 0][arow] = av.x;
        As[akq + 1][arow] = av.y;
        As[akq + 2][arow] = av.z;
        As[akq + 3][arow] = av.w;
        *reinterpret_cast<float4*>(&Bs[bk][bq]) = bv;
        __syncthreads();

#pragma unroll
        for (int kk = 0; kk < BK; ++kk) {
            float4 a = *reinterpret_cast<const float4*>(&As[kk][ty * 4]);
            float4 b = *reinterpret_cast<const float4*>(&Bs[kk][tx * 4]);
            acc[0][0] += a.x * b.x; acc[0][1] += a.x * b.y; acc[0][2] += a.x * b.z; acc[0][3] += a.x * b.w;
            acc[1][0] += a.y * b.x; acc[1][1] += a.y * b.y; acc[1][2] += a.y * b.z; acc[1][3] += a.y * b.w;
            acc[2][0] += a.z * b.x; acc[2][1] += a.z * b.y; acc[2][2] += a.z * b.z; acc[2][3] += a.z * b.w;
            acc[3][0] += a.w * b.x; acc[3][1] += a.w * b.y; acc[3][2] += a.w * b.z; acc[3][3] += a.w * b.w;
        }
    }

    const int grow = bm * BM + ty * 4;
    const int gcol = bn * BN + tx * 4;
#pragma unroll
    for (int i = 0; i < 4; ++i) {
#pragma unroll
        for (int j = 0; j < 4; ++j) {
            int r = grow + i, c = gcol + j;
            int idx = r * HID + c;
            float I  = acc[i][j] + b1[c];
            float vp = (t == 0) ? 0.0f : g_vhid[idx];
            float v  = vp + (I - vp) * 0.5f;
            float spk = ((v - 1.0f) >= 0.0f) ? 1.0f : 0.0f;
            v = v * (1.0f - spk);
            g_vhid[idx] = v;
            float contrib = ct * spk;
            if (t == 0) g_spkacc[idx] = contrib;
            else        g_spkacc[idx] += contrib;
        }
    }
}

// ---------------------------------------------------------------------------
// Kernel 3: readout — v_out = g_spkacc @ Wr + (1 - 2^-10) * br
// ---------------------------------------------------------------------------
__global__ __launch_bounds__(256)
void readout_kernel(const float* __restrict__ Wr,
                    const float* __restrict__ br,
                    float* __restrict__ out) {
    __shared__ float As[BK][BM + APAD];
    __shared__ float Bs[BK][48];

    const int tid = threadIdx.x;
    const int bm  = blockIdx.x;
    const int tx  = tid & 15;
    const int ty  = tid >> 4;

    const float* Abase = g_spkacc + (size_t)bm * BM * HID;
    const int arow = tid >> 2;
    const int akq  = (tid & 3) * 4;

    float acc[4][3] = {};

    for (int k0 = 0; k0 < HID; k0 += BK) {
        float4 av = *reinterpret_cast<const float4*>(Abase + (size_t)arow * HID + k0 + akq);
        float bvals[3];
#pragma unroll
        for (int p = 0; p < 3; ++p) {
            int idx = tid + p * 256;
            int kk = idx / 48, cc = idx % 48;
            bvals[p] = (cc < NCLS) ? Wr[(size_t)(k0 + kk) * NCLS + cc] : 0.0f;
        }

        __syncthreads();
        As[akq + 0][arow] = av.x;
        As[akq + 1][arow] = av.y;
        As[akq + 2][arow] = av.z;
        As[akq + 3][arow] = av.w;
#pragma unroll
        for (int p = 0; p < 3; ++p) {
            int idx = tid + p * 256;
            Bs[idx / 48][idx % 48] = bvals[p];
        }
        __syncthreads();

#pragma unroll
        for (int kk = 0; kk < BK; ++kk) {
            float4 a = *reinterpret_cast<const float4*>(&As[kk][ty * 4]);
            float b0  = Bs[kk][tx * 3 + 0];
            float b1v = Bs[kk][tx * 3 + 1];
            float b2  = Bs[kk][tx * 3 + 2];
            acc[0][0] += a.x * b0; acc[0][1] += a.x * b1v; acc[0][2] += a.x * b2;
            acc[1][0] += a.y * b0; acc[1][1] += a.y * b1v; acc[1][2] += a.y * b2;
            acc[2][0] += a.z * b0; acc[2][1] += a.z * b1v; acc[2][2] += a.z * b2;
            acc[3][0] += a.w * b0; acc[3][1] += a.w * b1v; acc[3][2] += a.w * b2;
        }
    }

    const float brc = 1.0f - 0x1p-10f;
    const int grow = bm * BM + ty * 4;
#pragma unroll
    for (int i = 0; i < 4; ++i) {
#pragma unroll
        for (int j = 0; j < 3; ++j) {
            int c = tx * 3 + j;
            if (c < NCLS) {
                out[(size_t)(grow + i) * NCLS + c] = acc[i][j] + brc * br[c];
            }
        }
    }
}

// ---------------------------------------------------------------------------
extern "C" void kernel_launch(void* const* d_in, const int* in_sizes, int n_in,
                              void* d_out, int out_size) {
    // Identify inputs by element count (all sizes distinct) — immune to ordering.
    const float *x = nullptr, *W1 = nullptr, *b1 = nullptr, *Wr = nullptr, *br = nullptr;
    for (int i = 0; i < n_in; ++i) {
        const float* p = (const float*)d_in[i];
        switch (in_sizes[i]) {
            case BATCH * IN_DIM: x  = p; break;   // 3,211,264
            case IN_DIM * HID:   W1 = p; break;   // 200,704
            case HID:            b1 = p; break;   // 256
            case HID * NCLS:     Wr = p; break;   // 12,032
            case NCLS:           br = p; break;   // 47
        }
    }
    float* out = (float*)d_out;

    rng_spikes_kernel<<<RNG_GRID, 256>>>(x);

    for (int t = 0; t < T_STEPS; ++t) {
        float ct = ldexpf(1.0f, t - T_STEPS);  // 2^(t-10), exact
        hidden_kernel<<<dim3(BATCH / BM, HID / BN), 256>>>(W1, b1, t, ct);
    }

    readout_kernel<<<BATCH / BM, 256>>>(Wr, br, out);
}

// round 4
// speedup vs baseline: 3.0757x; 3.0757x over previous
#include <cuda_runtime.h>
#include <cuda_bf16.h>
#include <cstdint>

#define T_STEPS 10
#define IN_DIM  784
#define HID     256
#define NCLS    47
#define BATCH   4096
#define MROWS   (T_STEPS * BATCH)     /* 40960 */
#define KPAD    832                   /* 784 padded to 13*64 */

// Static device scratch (no cudaMalloc anywhere)
__device__ __nv_bfloat16 g_spk[(size_t)MROWS * KPAD];   // 68MB bf16 spikes, padded
__device__ __nv_bfloat16 g_Bcat[768 * KPAD];            // [W1hi; W1mid; W1lo] K-major
__device__ float g_I[(size_t)MROWS * HID];              // 42MB GEMM output (no bias)
__device__ float g_spkacc[BATCH * HID];                 // Sum_t 2^(t-10) spk_t

// ---------------------------------------------------------------------------
// RNG: JAX partitionable threefry2x32, key (0,42) -> bf16 Bernoulli spikes
// ---------------------------------------------------------------------------
__device__ __forceinline__ uint32_t rotl32_(uint32_t x, int d) {
    return __funnelshift_l(x, x, d);
}
__device__ __forceinline__ float u01_(uint32_t b) {
    return __uint_as_float((b >> 9) | 0x3f800000u) - 1.0f;
}
__device__ __forceinline__ uint32_t threefry_xor(uint32_t i) {
    uint32_t x0 = 0u, x1 = i;
    const uint32_t ks0 = 0u, ks1 = 42u, ks2 = 42u ^ 0x1BD11BDAu;
    x0 += ks0; x1 += ks1;
#define RND(r) { x0 += x1; x1 = rotl32_(x1, r); x1 ^= x0; }
    RND(13) RND(15) RND(26) RND(6)   x0 += ks1; x1 += ks2 + 1u;
    RND(17) RND(29) RND(16) RND(24)  x0 += ks2; x1 += ks0 + 2u;
    RND(13) RND(15) RND(26) RND(6)   x0 += ks0; x1 += ks1 + 3u;
    RND(17) RND(29) RND(16) RND(24)  x0 += ks1; x1 += ks2 + 4u;
    RND(13) RND(15) RND(26) RND(6)   x0 += ks2; x1 += ks0 + 5u;
#undef RND
    return x0 ^ x1;
}

__global__ __launch_bounds__(256)
void rng_kernel(const float* __restrict__ x) {
    uint32_t tau = blockIdx.x * 256 + threadIdx.x;   // < 40960*208
    uint32_t row = tau / 208;
    uint32_t q   = (tau % 208) * 4;                  // 784 % 4 == 0: no straddle
    ushort4 o;
    if (q >= IN_DIM) {
        o = make_ushort4(0, 0, 0, 0);
    } else {
        uint32_t ib = row * IN_DIM + q;              // JAX flat index (t*B+b)*784 + j
        const float4 px = *reinterpret_cast<const float4*>(
            x + (size_t)(row & (BATCH - 1)) * IN_DIM + q);
        o.x = (u01_(threefry_xor(ib + 0)) < px.x) ? 0x3F80 : 0;
        o.y = (u01_(threefry_xor(ib + 1)) < px.y) ? 0x3F80 : 0;
        o.z = (u01_(threefry_xor(ib + 2)) < px.z) ? 0x3F80 : 0;
        o.w = (u01_(threefry_xor(ib + 3)) < px.w) ? 0x3F80 : 0;
    }
    *reinterpret_cast<ushort4*>(
        reinterpret_cast<unsigned short*>(g_spk) + (size_t)row * KPAD + q) = o;
}

// ---------------------------------------------------------------------------
// Split W1 (fp32 [784,256]) into exact bf16 triple, K-major, zero-padded.
// ---------------------------------------------------------------------------
__global__ __launch_bounds__(256)
void split_kernel(const float* __restrict__ W1) {
    uint32_t tau = blockIdx.x * 256 + threadIdx.x;   // < 832*256
    uint32_t k = tau % KPAD;
    uint32_t n = tau / KPAD;
    __nv_bfloat16 hi = __float2bfloat16(0.0f), mid = hi, lo = hi;
    if (k < IN_DIM) {
        float w = W1[k * HID + n];
        hi = __float2bfloat16(w);
        float r1 = w - __bfloat162float(hi);                 // exact
        mid = __float2bfloat16(r1);
        lo = __float2bfloat16(r1 - __bfloat162float(mid));   // exact
    }
    g_Bcat[(0 * HID + n) * KPAD + k] = hi;
    g_Bcat[(1 * HID + n) * KPAD + k] = mid;
    g_Bcat[(2 * HID + n) * KPAD + k] = lo;
}

// ---------------------------------------------------------------------------
// bf16 mma.sync GEMM: I[40960,256] = spk @ (hi+mid+lo)   [all into one acc]
// CTA 128x128, 8 warps (4Mx2N), warp 32x64, K-chunk 64, 2-stage cp.async.
// B stage holds all 3 splits (A tile reused across splits).
// ---------------------------------------------------------------------------
#define NCHUNK 13
#define A_ST   16384                    /* 128 rows x 128B */
#define B_ST   49152                    /* 3 x 128 rows x 128B */
#define STAGE_B (A_ST + B_ST)           /* 65536 */
#define SMEM_G  (2 * STAGE_B)           /* 131072 */
#define SWZ(o) ((o) ^ (((o) >> 3) & 0x70))

__device__ __forceinline__ uint32_t s2u(const void* p) {
    uint32_t a;
    asm("{ .reg .u64 t; cvta.to.shared.u64 t, %1; cvt.u32.u64 %0, t; }"
        : "=r"(a) : "l"(p));
    return a;
}
__device__ __forceinline__ void cp16(uint32_t dst, const void* src) {
    asm volatile("cp.async.cg.shared.global [%0], [%1], 16;"
                 :: "r"(dst), "l"(__cvta_generic_to_global(src)));
}
__device__ __forceinline__ void ldsm4(uint32_t& r0, uint32_t& r1,
                                      uint32_t& r2, uint32_t& r3, uint32_t addr) {
    asm volatile("ldmatrix.sync.aligned.m8n8.x4.shared.b16 {%0,%1,%2,%3}, [%4];"
                 : "=r"(r0), "=r"(r1), "=r"(r2), "=r"(r3) : "r"(addr));
}
__device__ __forceinline__ void mma16816(float* c, const uint32_t* a,
                                         uint32_t b0, uint32_t b1) {
    asm volatile("mma.sync.aligned.m16n8k16.row.col.f32.bf16.bf16.f32 "
                 "{%0,%1,%2,%3}, {%4,%5,%6,%7}, {%8,%9}, {%0,%1,%2,%3};"
                 : "+f"(c[0]), "+f"(c[1]), "+f"(c[2]), "+f"(c[3])
                 : "r"(a[0]), "r"(a[1]), "r"(a[2]), "r"(a[3]), "r"(b0), "r"(b1));
}

__device__ __forceinline__ void load_stage(int c, int st, int tid, uint32_t sb,
                                           const __nv_bfloat16* Ag, int tile_n) {
    uint32_t ab = sb + st * STAGE_B;
    uint32_t bb = ab + A_ST;
    const __nv_bfloat16* As = Ag + c * 64;
    const __nv_bfloat16* Bs = g_Bcat + (size_t)tile_n * 128 * KPAD + c * 64;
#pragma unroll
    for (int it = 0; it < 16; ++it) {                 // 4096 16B chunks / 256 thr
        int idx = tid + it * 256;
        if (idx < 1024) {                             // A: 128 rows x 8 chunks
            int r = idx >> 3, ch = idx & 7;
            cp16(ab + SWZ(r * 128 + ch * 16), As + (size_t)r * KPAD + ch * 8);
        } else {                                      // B: 3 splits x 128 rows x 8
            int j = idx - 1024;
            int s = j >> 10, jj = j & 1023;
            int r = jj >> 3, ch = jj & 7;
            cp16(bb + s * A_ST + SWZ(r * 128 + ch * 16),
                 Bs + ((size_t)s * HID + r) * KPAD + ch * 8);
        }
    }
    asm volatile("cp.async.commit_group;" ::: "memory");
}

__global__ __launch_bounds__(256)
void gemm_kernel() {
    extern __shared__ char smem[];
    uint32_t sb = s2u(smem);
    const int tid = threadIdx.x;
    const int wid = tid >> 5, lane = tid & 31;
    const int warp_m = wid & 3, warp_n = wid >> 2;
    const int tile_m = blockIdx.x, tile_n = blockIdx.y;

    const __nv_bfloat16* Ag = g_spk + (size_t)tile_m * 128 * KPAD;

    float acc[2][8][4] = {};

    load_stage(0, 0, tid, sb, Ag, tile_n);

    // ldmatrix lane address components (constant over loop)
    const int arow = warp_m * 32 + (lane & 15);
    const int akh  = (lane >> 4) * 8;                          // A k-half
    const int nrow = warp_n * 64 + (lane & 7) + ((lane & 16) ? 8 : 0);
    const int bkh  = (lane & 8) ? 8 : 0;                       // B k-half

    for (int c = 0; c < NCHUNK; ++c) {
        const int st = c & 1;
        if (c + 1 < NCHUNK) {
            load_stage(c + 1, st ^ 1, tid, sb, Ag, tile_n);
            asm volatile("cp.async.wait_group 1;" ::: "memory");
        } else {
            asm volatile("cp.async.wait_group 0;" ::: "memory");
        }
        __syncthreads();

        uint32_t sA = sb + st * STAGE_B;
        uint32_t sB = sA + A_ST;
#pragma unroll
        for (int ks = 0; ks < 4; ++ks) {
            uint32_t a0[4], a1[4];
            ldsm4(a0[0], a0[1], a0[2], a0[3],
                  sA + SWZ(arow * 128 + (ks * 16 + akh) * 2));
            ldsm4(a1[0], a1[1], a1[2], a1[3],
                  sA + SWZ((arow + 16) * 128 + (ks * 16 + akh) * 2));
#pragma unroll
            for (int s = 0; s < 3; ++s) {
                uint32_t sBs = sB + s * A_ST;
#pragma unroll
                for (int g = 0; g < 4; ++g) {
                    uint32_t r0, r1, r2, r3;
                    ldsm4(r0, r1, r2, r3,
                          sBs + SWZ((nrow + g * 16) * 128 + (ks * 16 + bkh) * 2));
                    mma16816(acc[0][g * 2 + 0], a0, r0, r1);
                    mma16816(acc[1][g * 2 + 0], a1, r0, r1);
                    mma16816(acc[0][g * 2 + 1], a0, r2, r3);
                    mma16816(acc[1][g * 2 + 1], a1, r2, r3);
                }
            }
        }
        __syncthreads();
    }

    // Epilogue: write fp32 result
    const int rbase = tile_m * 128 + warp_m * 32 + (lane >> 2);
    const int cbase = tile_n * 128 + warp_n * 64 + (lane & 3) * 2;
#pragma unroll
    for (int mf = 0; mf < 2; ++mf) {
#pragma unroll
        for (int nf = 0; nf < 8; ++nf) {
            int r = rbase + mf * 16;
            int cc = cbase + nf * 8;
            *reinterpret_cast<float2*>(g_I + (size_t)r * HID + cc) =
                make_float2(acc[mf][nf][0], acc[mf][nf][1]);
            *reinterpret_cast<float2*>(g_I + (size_t)(r + 8) * HID + cc) =
                make_float2(acc[mf][nf][2], acc[mf][nf][3]);
        }
    }
}

// ---------------------------------------------------------------------------
// LIF recurrence scan: thread per (b,h); identical arithmetic to R2 epilogue.
// ---------------------------------------------------------------------------
__global__ __launch_bounds__(256)
void scan_kernel(const float* __restrict__ b1) {
    int tau = blockIdx.x * 256 + threadIdx.x;  // < 4096*256
    int b = tau >> 8, h = tau & 255;
    float bias = b1[h];
    float v = 0.0f, acc = 0.0f;
#pragma unroll
    for (int t = 0; t < T_STEPS; ++t) {
        float I = g_I[((size_t)t * BATCH + b) * HID + h] + bias;
        v = v + (I - v) * 0.5f;
        float spk = ((v - 1.0f) >= 0.0f) ? 1.0f : 0.0f;
        v = v * (1.0f - spk);
        const float ct = (float)(1 << t) * 0x1p-10f;   // 2^(t-10), exact
        acc += ct * spk;
    }
    g_spkacc[tau] = acc;
}

// ---------------------------------------------------------------------------
// Readout: v_out = g_spkacc @ Wr + (1 - 2^-10) * br
// ---------------------------------------------------------------------------
#define BM 64
#define BK 16
#define APAD 4

__global__ __launch_bounds__(256)
void readout_kernel(const float* __restrict__ Wr,
                    const float* __restrict__ br,
                    float* __restrict__ out) {
    __shared__ float As[BK][BM + APAD];
    __shared__ float Bs[BK][48];

    const int tid = threadIdx.x;
    const int bm  = blockIdx.x;
    const int tx  = tid & 15;
    const int ty  = tid >> 4;

    const float* Abase = g_spkacc + (size_t)bm * BM * HID;
    const int arow = tid >> 2;
    const int akq  = (tid & 3) * 4;

    float acc[4][3] = {};

    for (int k0 = 0; k0 < HID; k0 += BK) {
        float4 av = *reinterpret_cast<const float4*>(Abase + (size_t)arow * HID + k0 + akq);
        float bvals[3];
#pragma unroll
        for (int p = 0; p < 3; ++p) {
            int idx = tid + p * 256;
            int kk = idx / 48, cc = idx % 48;
            bvals[p] = (cc < NCLS) ? Wr[(size_t)(k0 + kk) * NCLS + cc] : 0.0f;
        }
        __syncthreads();
        As[akq + 0][arow] = av.x;
        As[akq + 1][arow] = av.y;
        As[akq + 2][arow] = av.z;
        As[akq + 3][arow] = av.w;
#pragma unroll
        for (int p = 0; p < 3; ++p) {
            int idx = tid + p * 256;
            Bs[idx / 48][idx % 48] = bvals[p];
        }
        __syncthreads();
#pragma unroll
        for (int kk = 0; kk < BK; ++kk) {
            float4 a = *reinterpret_cast<const float4*>(&As[kk][ty * 4]);
            float b0  = Bs[kk][tx * 3 + 0];
            float b1v = Bs[kk][tx * 3 + 1];
            float b2  = Bs[kk][tx * 3 + 2];
            acc[0][0] += a.x * b0; acc[0][1] += a.x * b1v; acc[0][2] += a.x * b2;
            acc[1][0] += a.y * b0; acc[1][1] += a.y * b1v; acc[1][2] += a.y * b2;
            acc[2][0] += a.z * b0; acc[2][1] += a.z * b1v; acc[2][2] += a.z * b2;
            acc[3][0] += a.w * b0; acc[3][1] += a.w * b1v; acc[3][2] += a.w * b2;
        }
    }

    const float brc = 1.0f - 0x1p-10f;
    const int grow = bm * BM + ty * 4;
#pragma unroll
    for (int i = 0; i < 4; ++i) {
#pragma unroll
        for (int j = 0; j < 3; ++j) {
            int c = tx * 3 + j;
            if (c < NCLS) {
                out[(size_t)(grow + i) * NCLS + c] = acc[i][j] + brc * br[c];
            }
        }
    }
}

// ---------------------------------------------------------------------------
extern "C" void kernel_launch(void* const* d_in, const int* in_sizes, int n_in,
                              void* d_out, int out_size) {
    const float *x = nullptr, *W1 = nullptr, *b1 = nullptr, *Wr = nullptr, *br = nullptr;
    for (int i = 0; i < n_in; ++i) {
        const float* p = (const float*)d_in[i];
        switch (in_sizes[i]) {
            case BATCH * IN_DIM: x  = p; break;
            case IN_DIM * HID:   W1 = p; break;
            case HID:            b1 = p; break;
            case HID * NCLS:     Wr = p; break;
            case NCLS:           br = p; break;
        }
    }
    float* out = (float*)d_out;

    cudaFuncSetAttribute(gemm_kernel,
                         cudaFuncAttributeMaxDynamicSharedMemorySize, SMEM_G);

    rng_kernel<<<(MROWS * (KPAD / 4)) / 256, 256>>>(x);     // 33280 blocks
    split_kernel<<<(KPAD * HID) / 256, 256>>>(W1);          // 832 blocks
    gemm_kernel<<<dim3(MROWS / 128, 2), 256, SMEM_G>>>();   // 640 CTAs
    scan_kernel<<<(BATCH * HID) / 256, 256>>>(b1);          // 4096 blocks
    readout_kernel<<<BATCH / BM, 256>>>(Wr, br, out);       // 64 blocks
}